// round 16
// baseline (speedup 1.0000x reference)
#include <cuda_runtime.h>
#include <cuda_bf16.h>
#include <cuda_fp16.h>
#include <cstdint>
#include <math.h>

#define NTOT 65536
#define BG   64
#define NPG  1024
#define ETOT 1048576
#define EPG  (ETOT / BG)     // 16384 edges per graph
#define DD   128
#define KK   512             // NPG/2

// ---------------- scratch (device globals: allocation-free) ----------------
#define AFSZ ((size_t)(NTOT / 16) * 8 * 32 * 4)
__device__ uint32_t g_afh[AFSZ];                    // agg hi fragments (bf16x2)
__device__ uint32_t g_afl[AFSZ];                    // agg lo fragments
__device__ __half2 g_xh[(size_t)NTOT * (DD / 2)];   // x in fp16 pairs (gather input)
__device__ __half2 g_oh[(size_t)NTOT * (DD / 2)];   // relu(conv output), fp16 pairs
__device__ float g_dinv[NTOT];
__device__ float g_scorep[2 * NTOT];                // per-half score partials
__device__ float g_pinv;
__device__ int   g_off[NTOT + 1];
__device__ int2  g_epack[ETOT];                     // {src_local, norm bits} by dst

// ========== zero the output (capture-legal) ==========
__global__ void k_zero_out(float* __restrict__ out) {
    int i = blockIdx.x * blockDim.x + threadIdx.x;
    if (i < BG * DD) out[i] = 0.0f;
}

// ========== convert x to fp16 (halves gather L2 traffic) ==========
__global__ void k_xconv(const float* __restrict__ x) {
    int i = blockIdx.x * blockDim.x + threadIdx.x;   // float4 chunks
    if (i >= NTOT * 32) return;
    float4 v = ((const float4*)x)[i];
    __half2 h0 = __floats2half2_rn(v.x, v.y);
    __half2 h1 = __floats2half2_rn(v.z, v.w);
    g_xh[i * 2]     = h0;
    g_xh[i * 2 + 1] = h1;
}

// ========== fused per-graph CSR build + (block 0) p-norm ==========
__global__ __launch_bounds__(512) void k_build(const int* __restrict__ ei,
                                               const float* __restrict__ ew,
                                               const float* __restrict__ p) {
    __shared__ float sdeg[NPG];
    __shared__ int   scnt[NPG];
    __shared__ int   soff[NPG];
    __shared__ int   scur[NPG];
    __shared__ int   s2[512];

    int g = blockIdx.x;
    int t = threadIdx.x;
    int base_e = g * EPG;
    int base_n = g * NPG;
    const int* src = ei;
    const int* dst = ei + ETOT;

    if (g == 0 && t < 32) {
        float4 pv = ((const float4*)p)[t];
        float pp = pv.x * pv.x + pv.y * pv.y + pv.z * pv.z + pv.w * pv.w;
        #pragma unroll
        for (int off = 16; off > 0; off >>= 1) pp += __shfl_xor_sync(0xFFFFFFFFu, pp, off);
        if (t == 0) g_pinv = rsqrtf(pp);
    }

    #pragma unroll
    for (int i = t; i < NPG; i += 512) { sdeg[i] = 1.0f; scnt[i] = 0; }
    __syncthreads();

    for (int e = t; e < EPG; e += 512) {
        int d = dst[base_e + e] - base_n;
        atomicAdd(&sdeg[d], ew[base_e + e]);
        atomicAdd(&scnt[d], 1);
    }
    __syncthreads();

    #pragma unroll
    for (int i = t; i < NPG; i += 512)
        sdeg[i] = rsqrtf(fmaxf(sdeg[i], 1e-12f));
    __syncthreads();

    int c0 = scnt[2 * t], c1 = scnt[2 * t + 1];
    int pairsum = c0 + c1;
    s2[t] = pairsum;
    __syncthreads();
    for (int d = 1; d < 512; d <<= 1) {
        int u = (t >= d) ? s2[t - d] : 0;
        __syncthreads(); s2[t] += u; __syncthreads();
    }
    int excl = s2[t] - pairsum;
    soff[2 * t]     = excl;
    soff[2 * t + 1] = excl + c0;
    scur[2 * t]     = excl;
    scur[2 * t + 1] = excl + c0;
    __syncthreads();

    #pragma unroll
    for (int i = t; i < NPG; i += 512) {
        g_dinv[base_n + i] = sdeg[i];
        g_off[base_n + i]  = base_e + soff[i];
    }
    if (g == 0 && t == 0) g_off[NTOT] = ETOT;

    for (int e = t; e < EPG; e += 512) {
        int s = src[base_e + e] - base_n;
        int d = dst[base_e + e] - base_n;
        float nrm = sdeg[s] * ew[base_e + e] * sdeg[d];
        int pos = atomicAdd(&scur[d], 1);
        g_epack[base_e + pos] = make_int2(s, __float_as_int(nrm));
    }
}

// ========== gather: warp per node; fp16 x reads; writes A fragments ==========
__global__ void k_gather() {
    int gt   = blockIdx.x * blockDim.x + threadIdx.x;
    int node = gt >> 5;
    int lane = gt & 31;
    if (node >= NTOT) return;
    int base_n = node & ~(NPG - 1);

    const uint2* xh = (const uint2*)g_xh;    // row pitch: 32 uint2 (= 128 halves)
    float di = g_dinv[node];
    float c  = di * di;

    uint2 raw = xh[(size_t)node * 32 + lane];
    float2 f0 = __half22float2(*(__half2*)&raw.x);
    float2 f1 = __half22float2(*(__half2*)&raw.y);
    float4 acc = make_float4(c * f0.x, c * f0.y, c * f1.x, c * f1.y);

    int i0 = g_off[node], i1 = g_off[node + 1];
    for (int base = i0; base < i1; base += 32) {
        int nload = i1 - base; if (nload > 32) nload = 32;
        int2 pk = make_int2(0, 0);
        if (lane < nload) pk = g_epack[base + lane];
        int j = 0;
        for (; j + 4 <= nload; j += 4) {
            #pragma unroll
            for (int u = 0; u < 4; u++) {
                int   s  = base_n + __shfl_sync(0xFFFFFFFFu, pk.x, j + u);
                float nm = __int_as_float(__shfl_sync(0xFFFFFFFFu, pk.y, j + u));
                uint2 rv = xh[(size_t)s * 32 + lane];
                float2 v0 = __half22float2(*(__half2*)&rv.x);
                float2 v1 = __half22float2(*(__half2*)&rv.y);
                acc.x += nm * v0.x; acc.y += nm * v0.y;
                acc.z += nm * v1.x; acc.w += nm * v1.y;
            }
        }
        for (; j < nload; j++) {
            int   s  = base_n + __shfl_sync(0xFFFFFFFFu, pk.x, j);
            float nm = __int_as_float(__shfl_sync(0xFFFFFFFFu, pk.y, j));
            uint2 rv = xh[(size_t)s * 32 + lane];
            float2 v0 = __half22float2(*(__half2*)&rv.x);
            float2 v1 = __half22float2(*(__half2*)&rv.y);
            acc.x += nm * v0.x; acc.y += nm * v0.y;
            acc.z += nm * v1.x; acc.w += nm * v1.y;
        }
    }

    float a[4] = {acc.x, acc.y, acc.z, acc.w};
    uint16_t hu[4], lu[4];
    #pragma unroll
    for (int j = 0; j < 4; j++) {
        __nv_bfloat16 hb = __float2bfloat16_rn(a[j]);
        __nv_bfloat16 lb = __float2bfloat16_rn(a[j] - __bfloat162float(hb));
        hu[j] = __bfloat16_as_ushort(hb);
        lu[j] = __bfloat16_as_ushort(lb);
    }
    uint32_t hp0 = (uint32_t)hu[0] | ((uint32_t)hu[1] << 16);
    uint32_t hp1 = (uint32_t)hu[2] | ((uint32_t)hu[3] << 16);
    uint32_t lp0 = (uint32_t)lu[0] | ((uint32_t)lu[1] << 16);
    uint32_t lp1 = (uint32_t)lu[2] | ((uint32_t)lu[3] << 16);

    int mblk    = node >> 4;
    int mr      = node & 15;
    int qr      = mr & 7;
    int regbase = mr >> 3;
    int ks      = lane >> 2;
    int khalf   = (lane >> 1) & 1;
    int qc0     = (lane & 1) * 2;
    int reg     = regbase + (khalf ? 2 : 0);

    size_t idx0 = ((size_t)(mblk * 8 + ks) * 32 + qr * 4 + qc0) * 4 + reg;
    size_t idx1 = idx0 + 4;
    g_afh[idx0] = hp0; g_afh[idx1] = hp1;
    g_afl[idx0] = lp0; g_afl[idx1] = lp1;
}

// ========== tensor-core GEMM: 32 rows/warp (B-frag register reuse) ==========
#define AP 136
#define NH 64
#define SM_B_HI 0
#define SM_B_LO (NH * AP)
#define SM_F_OFF (2 * NH * AP * 2)
#define GTC_SMEM (SM_F_OFF + 2 * NH * 4)

__device__ __forceinline__ void bf16_split(float v, __nv_bfloat16& hi, __nv_bfloat16& lo) {
    hi = __float2bfloat16_rn(v);
    lo = __float2bfloat16_rn(v - __bfloat162float(hi));
}

__device__ __forceinline__ void mma_bf16(float* c, uint32_t a0, uint32_t a1, uint32_t a2,
                                         uint32_t a3, uint32_t b0, uint32_t b1) {
    asm volatile(
        "mma.sync.aligned.m16n8k16.row.col.f32.bf16.bf16.f32 "
        "{%0,%1,%2,%3}, {%4,%5,%6,%7}, {%8,%9}, {%0,%1,%2,%3};"
        : "+f"(c[0]), "+f"(c[1]), "+f"(c[2]), "+f"(c[3])
        : "r"(a0), "r"(a1), "r"(a2), "r"(a3), "r"(b0), "r"(b1));
}

__global__ __launch_bounds__(256, 2) void k_gemm_mma(const float* __restrict__ W,
                                                     const float* __restrict__ bvec,
                                                     const float* __restrict__ pvec) {
    extern __shared__ __nv_bfloat16 smb[];
    __nv_bfloat16* Bh = smb + SM_B_HI;
    __nv_bfloat16* Bl = smb + SM_B_LO;
    float* bs = (float*)((char*)smb + SM_F_OFF);
    float* ps = bs + NH;

    int tid = threadIdx.x;
    int rb  = (blockIdx.x >> 1) * 256;
    int nh  = blockIdx.x & 1;

    for (int i = tid; i < 128 * 16; i += 256) {
        int k = i >> 4, q = i & 15;
        float4 v = *(const float4*)&W[(size_t)k * DD + nh * NH + q * 4];
        float vv[4] = {v.x, v.y, v.z, v.w};
        #pragma unroll
        for (int j = 0; j < 4; j++) {
            __nv_bfloat16 hi, lo;
            bf16_split(vv[j], hi, lo);
            Bh[(q * 4 + j) * AP + k] = hi;
            Bl[(q * 4 + j) * AP + k] = lo;
        }
    }
    if (tid < NH) { bs[tid] = bvec[nh * NH + tid]; ps[tid] = pvec[nh * NH + tid]; }

    int w  = tid >> 5;
    int l  = tid & 31;
    int qr = l >> 2;
    int qc = l & 3;

    int mblk0 = (rb >> 4) + 2 * w;
    const uint4* AFH0 = (const uint4*)g_afh + (size_t)(mblk0 * 8) * 32 + l;
    const uint4* AFL0 = (const uint4*)g_afl + (size_t)(mblk0 * 8) * 32 + l;
    const uint4* AFH1 = AFH0 + 8 * 32;
    const uint4* AFL1 = AFL0 + 8 * 32;

    float acc[2][8][4];
    #pragma unroll
    for (int m = 0; m < 2; m++)
        #pragma unroll
        for (int t = 0; t < 8; t++)
            #pragma unroll
            for (int j = 0; j < 4; j++) acc[m][t][j] = 0.0f;

    __syncthreads();

    #pragma unroll
    for (int ks = 0; ks < 8; ks++) {
        int k0 = ks * 16;
        uint4 ah0 = AFH0[ks * 32];
        uint4 al0 = AFL0[ks * 32];
        uint4 ah1 = AFH1[ks * 32];
        uint4 al1 = AFL1[ks * 32];

        #pragma unroll
        for (int t = 0; t < 8; t++) {
            const __nv_bfloat16* brow  = Bh + (t * 8 + qr) * AP;
            const __nv_bfloat16* browl = Bl + (t * 8 + qr) * AP;
            uint32_t bh0 = *(const uint32_t*)(brow  + k0 + qc * 2);
            uint32_t bh1 = *(const uint32_t*)(brow  + k0 + 8 + qc * 2);
            uint32_t bl0 = *(const uint32_t*)(browl + k0 + qc * 2);
            uint32_t bl1 = *(const uint32_t*)(browl + k0 + 8 + qc * 2);
            mma_bf16(acc[0][t], ah0.x, ah0.y, ah0.z, ah0.w, bh0, bh1);
            mma_bf16(acc[0][t], ah0.x, ah0.y, ah0.z, ah0.w, bl0, bl1);
            mma_bf16(acc[0][t], al0.x, al0.y, al0.z, al0.w, bh0, bh1);
            mma_bf16(acc[1][t], ah1.x, ah1.y, ah1.z, ah1.w, bh0, bh1);
            mma_bf16(acc[1][t], ah1.x, ah1.y, ah1.z, ah1.w, bl0, bl1);
            mma_bf16(acc[1][t], al1.x, al1.y, al1.z, al1.w, bh0, bh1);
        }
    }

    #pragma unroll
    for (int m = 0; m < 2; m++) {
        int r0 = rb + w * 32 + m * 16 + qr;
        int r1 = r0 + 8;
        float s0 = 0.0f, s1 = 0.0f;
        #pragma unroll
        for (int t = 0; t < 8; t++) {
            int cl = t * 8 + qc * 2;
            int cg = nh * NH + cl;
            float b0 = bs[cl], b1 = bs[cl + 1];
            float p0 = ps[cl], p1 = ps[cl + 1];
            float v00 = fmaxf(acc[m][t][0] + b0, 0.0f);
            float v01 = fmaxf(acc[m][t][1] + b1, 0.0f);
            float v10 = fmaxf(acc[m][t][2] + b0, 0.0f);
            float v11 = fmaxf(acc[m][t][3] + b1, 0.0f);
            g_oh[(size_t)r0 * (DD / 2) + (cg >> 1)] = __floats2half2_rn(v00, v01);
            g_oh[(size_t)r1 * (DD / 2) + (cg >> 1)] = __floats2half2_rn(v10, v11);
            s0 += v00 * p0 + v01 * p1;
            s1 += v10 * p0 + v11 * p1;
        }
        s0 += __shfl_xor_sync(0xFFFFFFFFu, s0, 1);
        s0 += __shfl_xor_sync(0xFFFFFFFFu, s0, 2);
        s1 += __shfl_xor_sync(0xFFFFFFFFu, s1, 1);
        s1 += __shfl_xor_sync(0xFFFFFFFFu, s1, 2);
        if (qc == 0) {
            g_scorep[2 * r0 + nh] = s0;
            g_scorep[2 * r1 + nh] = s1;
        }
    }
}

// ========== fused pool: block = (graph, col-half, node-half); atomicAdd partials ==========
__global__ __launch_bounds__(512) void k_pool(float* __restrict__ out) {
    __shared__ uint32_t s_u[NPG];
    __shared__ float    s_w[NPG];
    __shared__ int      hist[256];
    __shared__ int      sB, sRem;
    __shared__ float2   s_part[16 * 32];

    int g  = blockIdx.x >> 2;
    int q  = (blockIdx.x >> 1) & 1;
    int nh = blockIdx.x & 1;
    int base = g * NPG;
    int t = threadIdx.x;

    float sc[2]; uint32_t u[2];
    #pragma unroll
    for (int j = 0; j < 2; j++) {
        int n = 2 * t + j;
        float v = (g_scorep[2 * (base + n)] + g_scorep[2 * (base + n) + 1]) * g_pinv;
        sc[j] = v;
        uint32_t b = __float_as_uint(v);
        b = (b & 0x80000000u) ? ~b : (b | 0x80000000u);
        u[j] = b;
        s_u[n] = b;
    }

    bool act[2] = {true, true}, gtS[2] = {false, false};
    int remaining = KK;

    #pragma unroll
    for (int shift = 24; shift >= 0; shift -= 8) {
        if (t < 256) hist[t] = 0;
        __syncthreads();
        int bin[2];
        #pragma unroll
        for (int j = 0; j < 2; j++) {
            bin[j] = (int)((u[j] >> shift) & 0xFFu);
            if (act[j]) atomicAdd(&hist[bin[j]], 1);
        }
        __syncthreads();
        if (t < 32) {
            int v[8], chunk = 0;
            #pragma unroll
            for (int j = 0; j < 8; j++) { v[j] = hist[t * 8 + j]; chunk += v[j]; }
            int run = chunk;
            #pragma unroll
            for (int o = 1; o < 32; o <<= 1) {
                int uu = __shfl_down_sync(0xFFFFFFFFu, run, o);
                if (t + o < 32) run += uu;
            }
            int s[9];
            s[8] = run - chunk;
            #pragma unroll
            for (int j = 7; j >= 0; j--) s[j] = s[j + 1] + v[j];
            #pragma unroll
            for (int j = 0; j < 8; j++) {
                if (s[j] >= remaining && s[j + 1] < remaining) {
                    sB = t * 8 + j;
                    sRem = remaining - s[j + 1];
                }
            }
        }
        __syncthreads();
        int B = sB; remaining = sRem;
        #pragma unroll
        for (int j = 0; j < 2; j++) {
            if (act[j]) {
                if (bin[j] > B) { gtS[j] = true; act[j] = false; }
                else if (bin[j] < B) act[j] = false;
            }
        }
        __syncthreads();
    }

    #pragma unroll
    for (int j = 0; j < 2; j++) {
        int n = 2 * t + j;
        float wgt = 0.0f;
        if (gtS[j]) {
            wgt = tanhf(sc[j]);
        } else if (act[j]) {
            uint32_t uth = u[j];
            int r = 0;
            for (int jj = 0; jj < n; jj++) if (s_u[jj] == uth) r++;
            if (r < remaining) wgt = tanhf(sc[j]);
        }
        s_w[n] = wgt;
    }
    __syncthreads();

    int lane = t & 31;
    int grp  = t >> 5;
    int n0 = nh * (NPG / 2);
    float2 part = make_float2(0.0f, 0.0f);
    #pragma unroll 4
    for (int n = n0 + grp; n < n0 + NPG / 2; n += 16) {
        float wn = s_w[n];
        if (wn != 0.0f) {
            float2 hv = __half22float2(g_oh[(size_t)(base + n) * (DD / 2) + q * 32 + lane]);
            part.x += wn * hv.x;
            part.y += wn * hv.y;
        }
    }
    s_part[grp * 32 + lane] = part;
    __syncthreads();

    if (t < 32) {
        float2 s = make_float2(0.0f, 0.0f);
        #pragma unroll
        for (int r = 0; r < 16; r++) {
            float2 v = s_part[r * 32 + t];
            s.x += v.x; s.y += v.y;
        }
        float* op = &out[g * DD + q * 64 + t * 2];
        atomicAdd(op,     s.x * (1.0f / (float)KK));
        atomicAdd(op + 1, s.y * (1.0f / (float)KK));
    }
}

// ---------------- launch ----------------
extern "C" void kernel_launch(void* const* d_in, const int* in_sizes, int n_in,
                              void* d_out, int out_size) {
    const float* x  = (const float*)d_in[0];
    const float* ew = (const float*)d_in[1];
    const float* W  = (const float*)d_in[2];
    const float* b  = (const float*)d_in[3];
    const float* p  = (const float*)d_in[4];
    const int*   ei = (const int*)d_in[5];
    float* out = (float*)d_out;

    static int s_attr_done = 0;
    if (!s_attr_done) {
        cudaFuncSetAttribute(k_gemm_mma, cudaFuncAttributeMaxDynamicSharedMemorySize, GTC_SMEM);
        s_attr_done = 1;
    }

    k_zero_out<<<(BG * DD + 255) / 256, 256>>>(out);
    k_xconv<<<(NTOT * 32) / 256, 256>>>(x);
    k_build<<<BG, 512>>>(ei, ew, p);
    k_gather<<<(NTOT * 32) / 256, 256>>>();
    k_gemm_mma<<<(NTOT / 256) * 2, 256, GTC_SMEM>>>(W, b, p);
    k_pool<<<BG * 4, 512>>>(out);
}

// round 17
// speedup vs baseline: 1.0622x; 1.0622x over previous
#include <cuda_runtime.h>
#include <cuda_bf16.h>
#include <cuda_fp16.h>
#include <cstdint>
#include <math.h>

#define NTOT 65536
#define BG   64
#define NPG  1024
#define ETOT 1048576
#define EPG  (ETOT / BG)     // 16384 edges per graph
#define DD   128
#define KK   512             // NPG/2

// ---------------- scratch (device globals: allocation-free) ----------------
#define AFSZ ((size_t)(NTOT / 16) * 8 * 32 * 4)
__device__ uint32_t g_afh[AFSZ];                    // agg hi fragments (bf16x2)
__device__ uint32_t g_afl[AFSZ];                    // agg lo fragments
__device__ __half2 g_xh[(size_t)NTOT * (DD / 2)];   // x in fp16 pairs (gather input)
__device__ __half2 g_oh[(size_t)NTOT * (DD / 2)];   // relu(conv output), fp16 pairs
__device__ float g_dinv[NTOT];
__device__ float g_scorep[2 * NTOT];                // per-half score partials
__device__ float g_pinv;
__device__ int   g_off[NTOT + 1];
__device__ int2  g_epack[ETOT];                     // {src_local*32, norm bits} by dst

// ========== convert x to fp16 + zero output (fused; capture-legal) ==========
__global__ void k_xconv(const float* __restrict__ x, float* __restrict__ out) {
    int i = blockIdx.x * blockDim.x + threadIdx.x;   // float4 chunks
    if (i < BG * DD) out[i] = 0.0f;
    if (i >= NTOT * 32) return;
    float4 v = ((const float4*)x)[i];
    g_xh[i * 2]     = __floats2half2_rn(v.x, v.y);
    g_xh[i * 2 + 1] = __floats2half2_rn(v.z, v.w);
}

// ========== fused per-graph CSR build + (block 0) p-norm ==========
__global__ __launch_bounds__(512) void k_build(const int* __restrict__ ei,
                                               const float* __restrict__ ew,
                                               const float* __restrict__ p) {
    __shared__ float sdeg[NPG];
    __shared__ int   scnt[NPG];
    __shared__ int   soff[NPG];
    __shared__ int   scur[NPG];
    __shared__ int   s2[512];

    int g = blockIdx.x;
    int t = threadIdx.x;
    int base_e = g * EPG;
    int base_n = g * NPG;
    const int* src = ei;
    const int* dst = ei + ETOT;

    if (g == 0 && t < 32) {
        float4 pv = ((const float4*)p)[t];
        float pp = pv.x * pv.x + pv.y * pv.y + pv.z * pv.z + pv.w * pv.w;
        #pragma unroll
        for (int off = 16; off > 0; off >>= 1) pp += __shfl_xor_sync(0xFFFFFFFFu, pp, off);
        if (t == 0) g_pinv = rsqrtf(pp);
    }

    #pragma unroll
    for (int i = t; i < NPG; i += 512) { sdeg[i] = 1.0f; scnt[i] = 0; }
    __syncthreads();

    for (int e = t; e < EPG; e += 512) {
        int d = dst[base_e + e] - base_n;
        atomicAdd(&sdeg[d], ew[base_e + e]);
        atomicAdd(&scnt[d], 1);
    }
    __syncthreads();

    #pragma unroll
    for (int i = t; i < NPG; i += 512)
        sdeg[i] = rsqrtf(fmaxf(sdeg[i], 1e-12f));
    __syncthreads();

    int c0 = scnt[2 * t], c1 = scnt[2 * t + 1];
    int pairsum = c0 + c1;
    s2[t] = pairsum;
    __syncthreads();
    for (int d = 1; d < 512; d <<= 1) {
        int u = (t >= d) ? s2[t - d] : 0;
        __syncthreads(); s2[t] += u; __syncthreads();
    }
    int excl = s2[t] - pairsum;
    soff[2 * t]     = excl;
    soff[2 * t + 1] = excl + c0;
    scur[2 * t]     = excl;
    scur[2 * t + 1] = excl + c0;
    __syncthreads();

    #pragma unroll
    for (int i = t; i < NPG; i += 512) {
        g_dinv[base_n + i] = sdeg[i];
        g_off[base_n + i]  = base_e + soff[i];
    }
    if (g == 0 && t == 0) g_off[NTOT] = ETOT;

    for (int e = t; e < EPG; e += 512) {
        int s = src[base_e + e] - base_n;
        int d = dst[base_e + e] - base_n;
        float nrm = sdeg[s] * ew[base_e + e] * sdeg[d];
        int pos = atomicAdd(&scur[d], 1);
        g_epack[base_e + pos] = make_int2(s * 32, __float_as_int(nrm));  // pre-scaled
    }
}

// ========== gather: warp/node; uniform edge loads (no shfl); fp16 rows ==========
__global__ void k_gather() {
    int gt   = blockIdx.x * blockDim.x + threadIdx.x;
    int node = gt >> 5;
    int lane = gt & 31;
    if (node >= NTOT) return;
    int base_n = node & ~(NPG - 1);

    const uint2* xh = (const uint2*)g_xh;         // row pitch: 32 uint2
    size_t xbase = (size_t)base_n * 32 + lane;    // graph base + lane column
    const int2* ep = g_epack;

    float di = g_dinv[node];
    float c  = di * di;
    uint2 raw = xh[(size_t)node * 32 + lane];
    float2 f0 = __half22float2(*(__half2*)&raw.x);
    float2 f1 = __half22float2(*(__half2*)&raw.y);
    float4 acc = make_float4(c * f0.x, c * f0.y, c * f1.x, c * f1.y);

    int i0 = g_off[node], i1 = g_off[node + 1];
    int i = i0;
    for (; i + 4 <= i1; i += 4) {
        int2 p0 = ep[i], p1 = ep[i + 1], p2 = ep[i + 2], p3 = ep[i + 3];
        uint2 r0 = xh[xbase + p0.x];
        uint2 r1 = xh[xbase + p1.x];
        uint2 r2 = xh[xbase + p2.x];
        uint2 r3 = xh[xbase + p3.x];
        float n0 = __int_as_float(p0.y), n1 = __int_as_float(p1.y);
        float n2 = __int_as_float(p2.y), n3 = __int_as_float(p3.y);
        float2 a0 = __half22float2(*(__half2*)&r0.x), b0 = __half22float2(*(__half2*)&r0.y);
        float2 a1 = __half22float2(*(__half2*)&r1.x), b1 = __half22float2(*(__half2*)&r1.y);
        float2 a2 = __half22float2(*(__half2*)&r2.x), b2 = __half22float2(*(__half2*)&r2.y);
        float2 a3 = __half22float2(*(__half2*)&r3.x), b3 = __half22float2(*(__half2*)&r3.y);
        acc.x += n0 * a0.x + n1 * a1.x + n2 * a2.x + n3 * a3.x;
        acc.y += n0 * a0.y + n1 * a1.y + n2 * a2.y + n3 * a3.y;
        acc.z += n0 * b0.x + n1 * b1.x + n2 * b2.x + n3 * b3.x;
        acc.w += n0 * b0.y + n1 * b1.y + n2 * b2.y + n3 * b3.y;
    }
    for (; i < i1; i++) {
        int2 pk = ep[i];
        uint2 rv = xh[xbase + pk.x];
        float nm = __int_as_float(pk.y);
        float2 v0 = __half22float2(*(__half2*)&rv.x);
        float2 v1 = __half22float2(*(__half2*)&rv.y);
        acc.x += nm * v0.x; acc.y += nm * v0.y;
        acc.z += nm * v1.x; acc.w += nm * v1.y;
    }

    float a[4] = {acc.x, acc.y, acc.z, acc.w};
    uint16_t hu[4], lu[4];
    #pragma unroll
    for (int j = 0; j < 4; j++) {
        __nv_bfloat16 hb = __float2bfloat16_rn(a[j]);
        __nv_bfloat16 lb = __float2bfloat16_rn(a[j] - __bfloat162float(hb));
        hu[j] = __bfloat16_as_ushort(hb);
        lu[j] = __bfloat16_as_ushort(lb);
    }
    uint32_t hp0 = (uint32_t)hu[0] | ((uint32_t)hu[1] << 16);
    uint32_t hp1 = (uint32_t)hu[2] | ((uint32_t)hu[3] << 16);
    uint32_t lp0 = (uint32_t)lu[0] | ((uint32_t)lu[1] << 16);
    uint32_t lp1 = (uint32_t)lu[2] | ((uint32_t)lu[3] << 16);

    int mblk    = node >> 4;
    int mr      = node & 15;
    int qr      = mr & 7;
    int regbase = mr >> 3;
    int ks      = lane >> 2;
    int khalf   = (lane >> 1) & 1;
    int qc0     = (lane & 1) * 2;
    int reg     = regbase + (khalf ? 2 : 0);

    size_t idx0 = ((size_t)(mblk * 8 + ks) * 32 + qr * 4 + qc0) * 4 + reg;
    size_t idx1 = idx0 + 4;
    g_afh[idx0] = hp0; g_afh[idx1] = hp1;
    g_afl[idx0] = lp0; g_afl[idx1] = lp1;
}

// ========== tensor-core GEMM: 32 rows/warp (B-frag register reuse) ==========
#define AP 136
#define NH 64
#define SM_B_HI 0
#define SM_B_LO (NH * AP)
#define SM_F_OFF (2 * NH * AP * 2)
#define GTC_SMEM (SM_F_OFF + 2 * NH * 4)

__device__ __forceinline__ void bf16_split(float v, __nv_bfloat16& hi, __nv_bfloat16& lo) {
    hi = __float2bfloat16_rn(v);
    lo = __float2bfloat16_rn(v - __bfloat162float(hi));
}

__device__ __forceinline__ void mma_bf16(float* c, uint32_t a0, uint32_t a1, uint32_t a2,
                                         uint32_t a3, uint32_t b0, uint32_t b1) {
    asm volatile(
        "mma.sync.aligned.m16n8k16.row.col.f32.bf16.bf16.f32 "
        "{%0,%1,%2,%3}, {%4,%5,%6,%7}, {%8,%9}, {%0,%1,%2,%3};"
        : "+f"(c[0]), "+f"(c[1]), "+f"(c[2]), "+f"(c[3])
        : "r"(a0), "r"(a1), "r"(a2), "r"(a3), "r"(b0), "r"(b1));
}

__global__ __launch_bounds__(256, 2) void k_gemm_mma(const float* __restrict__ W,
                                                     const float* __restrict__ bvec,
                                                     const float* __restrict__ pvec) {
    extern __shared__ __nv_bfloat16 smb[];
    __nv_bfloat16* Bh = smb + SM_B_HI;
    __nv_bfloat16* Bl = smb + SM_B_LO;
    float* bs = (float*)((char*)smb + SM_F_OFF);
    float* ps = bs + NH;

    int tid = threadIdx.x;
    int rb  = (blockIdx.x >> 1) * 256;
    int nh  = blockIdx.x & 1;

    for (int i = tid; i < 128 * 16; i += 256) {
        int k = i >> 4, q = i & 15;
        float4 v = *(const float4*)&W[(size_t)k * DD + nh * NH + q * 4];
        float vv[4] = {v.x, v.y, v.z, v.w};
        #pragma unroll
        for (int j = 0; j < 4; j++) {
            __nv_bfloat16 hi, lo;
            bf16_split(vv[j], hi, lo);
            Bh[(q * 4 + j) * AP + k] = hi;
            Bl[(q * 4 + j) * AP + k] = lo;
        }
    }
    if (tid < NH) { bs[tid] = bvec[nh * NH + tid]; ps[tid] = pvec[nh * NH + tid]; }

    int w  = tid >> 5;
    int l  = tid & 31;
    int qr = l >> 2;
    int qc = l & 3;

    int mblk0 = (rb >> 4) + 2 * w;
    const uint4* AFH0 = (const uint4*)g_afh + (size_t)(mblk0 * 8) * 32 + l;
    const uint4* AFL0 = (const uint4*)g_afl + (size_t)(mblk0 * 8) * 32 + l;
    const uint4* AFH1 = AFH0 + 8 * 32;
    const uint4* AFL1 = AFL0 + 8 * 32;

    float acc[2][8][4];
    #pragma unroll
    for (int m = 0; m < 2; m++)
        #pragma unroll
        for (int t = 0; t < 8; t++)
            #pragma unroll
            for (int j = 0; j < 4; j++) acc[m][t][j] = 0.0f;

    __syncthreads();

    #pragma unroll
    for (int ks = 0; ks < 8; ks++) {
        int k0 = ks * 16;
        uint4 ah0 = AFH0[ks * 32];
        uint4 al0 = AFL0[ks * 32];
        uint4 ah1 = AFH1[ks * 32];
        uint4 al1 = AFL1[ks * 32];

        #pragma unroll
        for (int t = 0; t < 8; t++) {
            const __nv_bfloat16* brow  = Bh + (t * 8 + qr) * AP;
            const __nv_bfloat16* browl = Bl + (t * 8 + qr) * AP;
            uint32_t bh0 = *(const uint32_t*)(brow  + k0 + qc * 2);
            uint32_t bh1 = *(const uint32_t*)(brow  + k0 + 8 + qc * 2);
            uint32_t bl0 = *(const uint32_t*)(browl + k0 + qc * 2);
            uint32_t bl1 = *(const uint32_t*)(browl + k0 + 8 + qc * 2);
            mma_bf16(acc[0][t], ah0.x, ah0.y, ah0.z, ah0.w, bh0, bh1);
            mma_bf16(acc[0][t], ah0.x, ah0.y, ah0.z, ah0.w, bl0, bl1);
            mma_bf16(acc[0][t], al0.x, al0.y, al0.z, al0.w, bh0, bh1);
            mma_bf16(acc[1][t], ah1.x, ah1.y, ah1.z, ah1.w, bh0, bh1);
            mma_bf16(acc[1][t], ah1.x, ah1.y, ah1.z, ah1.w, bl0, bl1);
            mma_bf16(acc[1][t], al1.x, al1.y, al1.z, al1.w, bh0, bh1);
        }
    }

    #pragma unroll
    for (int m = 0; m < 2; m++) {
        int r0 = rb + w * 32 + m * 16 + qr;
        int r1 = r0 + 8;
        float s0 = 0.0f, s1 = 0.0f;
        #pragma unroll
        for (int t = 0; t < 8; t++) {
            int cl = t * 8 + qc * 2;
            int cg = nh * NH + cl;
            float b0 = bs[cl], b1 = bs[cl + 1];
            float p0 = ps[cl], p1 = ps[cl + 1];
            float v00 = fmaxf(acc[m][t][0] + b0, 0.0f);
            float v01 = fmaxf(acc[m][t][1] + b1, 0.0f);
            float v10 = fmaxf(acc[m][t][2] + b0, 0.0f);
            float v11 = fmaxf(acc[m][t][3] + b1, 0.0f);
            g_oh[(size_t)r0 * (DD / 2) + (cg >> 1)] = __floats2half2_rn(v00, v01);
            g_oh[(size_t)r1 * (DD / 2) + (cg >> 1)] = __floats2half2_rn(v10, v11);
            s0 += v00 * p0 + v01 * p1;
            s1 += v10 * p0 + v11 * p1;
        }
        s0 += __shfl_xor_sync(0xFFFFFFFFu, s0, 1);
        s0 += __shfl_xor_sync(0xFFFFFFFFu, s0, 2);
        s1 += __shfl_xor_sync(0xFFFFFFFFu, s1, 1);
        s1 += __shfl_xor_sync(0xFFFFFFFFu, s1, 2);
        if (qc == 0) {
            g_scorep[2 * r0 + nh] = s0;
            g_scorep[2 * r1 + nh] = s1;
        }
    }
}

// ========== fused pool: block = (graph, col-half, node-half); atomicAdd partials ==========
__global__ __launch_bounds__(512) void k_pool(float* __restrict__ out) {
    __shared__ uint32_t s_u[NPG];
    __shared__ float    s_w[NPG];
    __shared__ int      hist[256];
    __shared__ int      sB, sRem;
    __shared__ float2   s_part[16 * 32];

    int g  = blockIdx.x >> 2;
    int q  = (blockIdx.x >> 1) & 1;
    int nh = blockIdx.x & 1;
    int base = g * NPG;
    int t = threadIdx.x;

    float sc[2]; uint32_t u[2];
    #pragma unroll
    for (int j = 0; j < 2; j++) {
        int n = 2 * t + j;
        float v = (g_scorep[2 * (base + n)] + g_scorep[2 * (base + n) + 1]) * g_pinv;
        sc[j] = v;
        uint32_t b = __float_as_uint(v);
        b = (b & 0x80000000u) ? ~b : (b | 0x80000000u);
        u[j] = b;
        s_u[n] = b;
    }

    bool act[2] = {true, true}, gtS[2] = {false, false};
    int remaining = KK;

    #pragma unroll
    for (int shift = 24; shift >= 0; shift -= 8) {
        if (t < 256) hist[t] = 0;
        __syncthreads();
        int bin[2];
        #pragma unroll
        for (int j = 0; j < 2; j++) {
            bin[j] = (int)((u[j] >> shift) & 0xFFu);
            if (act[j]) atomicAdd(&hist[bin[j]], 1);
        }
        __syncthreads();
        if (t < 32) {
            int v[8], chunk = 0;
            #pragma unroll
            for (int j = 0; j < 8; j++) { v[j] = hist[t * 8 + j]; chunk += v[j]; }
            int run = chunk;
            #pragma unroll
            for (int o = 1; o < 32; o <<= 1) {
                int uu = __shfl_down_sync(0xFFFFFFFFu, run, o);
                if (t + o < 32) run += uu;
            }
            int s[9];
            s[8] = run - chunk;
            #pragma unroll
            for (int j = 7; j >= 0; j--) s[j] = s[j + 1] + v[j];
            #pragma unroll
            for (int j = 0; j < 8; j++) {
                if (s[j] >= remaining && s[j + 1] < remaining) {
                    sB = t * 8 + j;
                    sRem = remaining - s[j + 1];
                }
            }
        }
        __syncthreads();
        int B = sB; remaining = sRem;
        #pragma unroll
        for (int j = 0; j < 2; j++) {
            if (act[j]) {
                if (bin[j] > B) { gtS[j] = true; act[j] = false; }
                else if (bin[j] < B) act[j] = false;
            }
        }
        __syncthreads();
    }

    #pragma unroll
    for (int j = 0; j < 2; j++) {
        int n = 2 * t + j;
        float wgt = 0.0f;
        if (gtS[j]) {
            wgt = tanhf(sc[j]);
        } else if (act[j]) {
            uint32_t uth = u[j];
            int r = 0;
            for (int jj = 0; jj < n; jj++) if (s_u[jj] == uth) r++;
            if (r < remaining) wgt = tanhf(sc[j]);
        }
        s_w[n] = wgt;
    }
    __syncthreads();

    int lane = t & 31;
    int grp  = t >> 5;
    int n0 = nh * (NPG / 2);
    float2 part = make_float2(0.0f, 0.0f);
    #pragma unroll 4
    for (int n = n0 + grp; n < n0 + NPG / 2; n += 16) {
        float wn = s_w[n];
        if (wn != 0.0f) {
            float2 hv = __half22float2(g_oh[(size_t)(base + n) * (DD / 2) + q * 32 + lane]);
            part.x += wn * hv.x;
            part.y += wn * hv.y;
        }
    }
    s_part[grp * 32 + lane] = part;
    __syncthreads();

    if (t < 32) {
        float2 s = make_float2(0.0f, 0.0f);
        #pragma unroll
        for (int r = 0; r < 16; r++) {
            float2 v = s_part[r * 32 + t];
            s.x += v.x; s.y += v.y;
        }
        float* op = &out[g * DD + q * 64 + t * 2];
        atomicAdd(op,     s.x * (1.0f / (float)KK));
        atomicAdd(op + 1, s.y * (1.0f / (float)KK));
    }
}

// ---------------- launch ----------------
extern "C" void kernel_launch(void* const* d_in, const int* in_sizes, int n_in,
                              void* d_out, int out_size) {
    const float* x  = (const float*)d_in[0];
    const float* ew = (const float*)d_in[1];
    const float* W  = (const float*)d_in[2];
    const float* b  = (const float*)d_in[3];
    const float* p  = (const float*)d_in[4];
    const int*   ei = (const int*)d_in[5];
    float* out = (float*)d_out;

    static int s_attr_done = 0;
    if (!s_attr_done) {
        cudaFuncSetAttribute(k_gemm_mma, cudaFuncAttributeMaxDynamicSharedMemorySize, GTC_SMEM);
        s_attr_done = 1;
    }

    k_xconv<<<(NTOT * 32) / 256, 256>>>(x, out);
    k_build<<<BG, 512>>>(ei, ew, p);
    k_gather<<<(NTOT * 32) / 256, 256>>>();
    k_gemm_mma<<<(NTOT / 256) * 2, 256, GTC_SMEM>>>(W, b, p);
    k_pool<<<BG * 4, 512>>>(out);
}